// round 17
// baseline (speedup 1.0000x reference)
#include <cuda_runtime.h>

// ---------------------------------------------------------------------------
// LocalGOCorrOpt: fused steepest-descent filter optimization.
// b=4, c=128, H=W=128, 9x9 search window (81 disps), 10 bins, 3 iterations.
// R17: producer-warp pattern (R16 win) ported to corr_t: 160 threads =
// 4 compute warps + 1 staging warp, double-buffered 16-ch chunks with two
// barriers per chunk (publish / free). corr kernels unchanged from R16.
// ---------------------------------------------------------------------------

#define NB 4
#define NC 128
#define NH 128
#define NW 128
#define NHW (NH*NW)
#define NS 9
#define ND 81
#define TX 32
#define TY 8
#define RST 44         // padded smem stride for ref window rows
#define FST 36         // padded smem stride for f / mapped rows

// ---------------- device scratch (no allocation allowed) -------------------
__device__ float g_scores[NB*ND*NHW];     // (b,81,H,W)
__device__ float g_fgrad[NB*NC*NHW];      // (b,c,H,W)
__device__ float g_f[NB*NC*NHW];          // current filter between iterations
__device__ float g_anum[NB*NHW];          // alpha numerator per pixel
__device__ float g_target[ND];
__device__ float g_vplus[ND];
__device__ float g_alo[ND];
__device__ float g_ahi[ND];
__device__ float g_step;
__device__ float g_reg;

// ---------------- per-displacement constants -------------------------------
__global__ void setup_kernel(const float* __restrict__ lw, const float* __restrict__ sw,
                             const float* __restrict__ mw, const float* __restrict__ ls,
                             const float* __restrict__ fr) {
    int d = threadIdx.x;
    if (d == 0) {
        g_step = expf(ls[0]);
        float rr = fr[0] * fr[0];
        g_reg = fmaxf(rr, 1e-10f) / (float)(NC * NC);
    }
    if (d < ND) {
        int dy = d / NS, dx = d % NS;
        float fy = (float)dy - 4.0f, fx = (float)dx - 4.0f;
        float dist = sqrtf(fy*fy + fx*fx) * 2.0f;   // / bin_displacement (0.5)
        float t = 0.f, vp = 0.f, m = 0.f;
        for (int k = 0; k < 10; k++) {
            float val;
            if (k == 9) val = fminf(fmaxf(dist - 8.0f, 0.0f), 1.0f);
            else        val = fmaxf(1.0f - fabsf(dist - (float)k), 0.0f);
            t  += val * lw[k];
            vp += val * sw[k];
            m  += val * mw[k];
        }
        float wm = 1.0f / (1.0f + expf(-m));        // sigmoid
        g_target[d] = t;
        g_vplus[d]  = vp;
        g_alo[d]    = (1.0f - wm) * 0.5f;
        g_ahi[d]    = (1.0f + wm) * 0.5f;
    }
}

// ---------------- cp.async helpers -----------------------------------------
__device__ __forceinline__ void cpa16(float* dst, const float* src, bool v) {
    unsigned s = (unsigned)__cvta_generic_to_shared(dst);
    int n = v ? 16 : 0;                  // src-size 0 -> zero-fill destination
    asm volatile("cp.async.cg.shared.global [%0], [%1], 16, %2;\n"
                 :: "r"(s), "l"(src), "r"(n));
}
__device__ __forceinline__ void cp_commit() {
    asm volatile("cp.async.commit_group;\n");
}
template<int N> __device__ __forceinline__ void cp_wait() {
    asm volatile("cp.async.wait_group %0;\n" :: "n"(N));
}
// i / 160 for 0 <= i < 4096
__device__ __forceinline__ int div160(int i) {
    return (int)(((unsigned)i * 52429u) >> 23);
}

// Build per-block ref-window staging table: for each of the 160 float4 slots
// of one channel's window: x = global spatial offset (or -1 if OOB zero-fill),
// y = smem offset within the channel's 704-float region.
__device__ __forceinline__ void build_ref_tbl(int2* tbl, int tid, int nthr,
                                              int x0, int y0) {
    for (int i = tid; i < 160; i += nthr) {
        int wy = i / 10, wx4 = i - wy*10;
        int h = y0 + wy - 4, w = x0 + wx4*4 - 4;
        bool v = ((unsigned)h < NH) && ((unsigned)w < NW);
        tbl[i] = make_int2(v ? (h*NW + w) : -1, wy*RST + wx4*4);
    }
}

// ---------------------------------------------------------------------------
// corr_kernel (unchanged from R16): scores(p,d) = sum_c f(c,p) * ref(c,p+d-4)
// 320 threads: warps 0-8 compute (warp w <-> dy=w, thread tile 8px x 9dx);
// warp 9 is a dedicated PRODUCER that does all cp.async staging.
// 8-ch chunks, 3-stage ring, 16 syncs.
// MODE 0: write g_scores.
// MODE 1: fin = f_grad; epilogue reduces alpha_den in smem, computes alpha,
//         and applies the filter update (fout = fbase - step*alpha*f_grad).
// ---------------------------------------------------------------------------
#define CBUF 7936
#define CORR_SMEM (3*CBUF*4 + 160*8)   // 95232 + 1280 = 96512 B

template<int MODE>
__global__ __launch_bounds__(320, 2)
void corr_kernel(const float* __restrict__ fin, const float* __restrict__ ref,
                 const float* __restrict__ fbase, float* __restrict__ fout)
{
    extern __shared__ float sm[];
    int2* tbl = (int2*)(sm + 3*CBUF);
    const int b  = blockIdx.z;
    const int x0 = blockIdx.x * TX, y0 = blockIdx.y * TY;
    const int tid = threadIdx.x;
    const int dy = tid >> 5;               // 0..8 compute, 9 producer
    const int r  = tid & 31;
    const int y  = r >> 2;
    const int xg = r & 3;
    const bool producer = (dy == 9);

    build_ref_tbl(tbl, tid, 320, x0, y0);
    __syncthreads();                       // table ready

    const float* refb = ref + b*NC*NHW;
    const float* finb = fin + ((b*NC)*NH + y0)*NW + x0;

    float acc[9][8];
#pragma unroll
    for (int a = 0; a < 9; a++)
#pragma unroll
        for (int j = 0; j < 8; j++) acc[a][j] = 0.f;

    if (producer) {
        // ---- staging-only warp: 16 groups of 8 channels, 3-stage ring ----
        const int lane = r;
        auto stage = [&](int s, int ch) {
            float* rb_ = sm + s*CBUF;
            float* fb_ = rb_ + 5632;
            const float* rc_ = refb + ch*NHW;
            for (int i = lane; i < 1280; i += 32) {
                int c_ = div160(i);
                int2 t_ = tbl[i - c_*160];
                bool v_ = (t_.x >= 0);
                const float* src_ = v_ ? (rc_ + c_*NHW + t_.x) : rc_;
                cpa16(rb_ + c_*704 + t_.y, src_, v_);
            }
            for (int i = lane; i < 512; i += 32) {
                int c_ = i >> 6, rem_ = i & 63;
                int yy_ = rem_ >> 3, x4_ = rem_ & 7;
                cpa16(fb_ + c_*288 + yy_*36 + x4_*4,
                      finb + (ch + c_)*NHW + yy_*NW + x4_*4, true);
            }
            cp_commit();
        };
        stage(0, 0);
        stage(1, 8);
        int bsg = 2;
        for (int ci = 0; ci < 16; ci++) {
            if (ci < 15) cp_wait<1>(); else cp_wait<0>();  // group ci landed
            __syncthreads();                               // publish to consumers
            if (ci < 14) {
                stage(bsg, (ci + 2)*8);
                bsg = (bsg == 2) ? 0 : bsg + 1;
            }
        }
    } else {
        // ---- compute warps: consume buffers in ring order ----
        int bc = 0;
        for (int ci = 0; ci < 16; ci++) {
            __syncthreads();               // wait for producer's group ci
#pragma unroll
            for (int cl = 0; cl < 8; cl++) {
                const float* rbuf = sm + bc*CBUF;
                const float* fbuf = rbuf + 5632;
                const float4* rp = (const float4*)(rbuf + cl*704 + (y+dy)*RST + xg*8);
                float4 ra = rp[0], rb4 = rp[1], rc4 = rp[2], rd4 = rp[3];
                float rv[16] = {ra.x,ra.y,ra.z,ra.w, rb4.x,rb4.y,rb4.z,rb4.w,
                                rc4.x,rc4.y,rc4.z,rc4.w, rd4.x,rd4.y,rd4.z,rd4.w};
                const float4* fp = (const float4*)(fbuf + cl*288 + y*36 + xg*8);
                float4 fa = fp[0], fb4 = fp[1];
                float fv[8] = {fa.x,fa.y,fa.z,fa.w, fb4.x,fb4.y,fb4.z,fb4.w};
#pragma unroll
                for (int dx = 0; dx < 9; dx++)
#pragma unroll
                    for (int j = 0; j < 8; j++)
                        acc[dx][j] = fmaf(fv[j], rv[dx + j], acc[dx][j]);
            }
            bc = (bc == 2) ? 0 : bc + 1;
        }
    }

    const int gh = y0 + y, gw = x0 + xg*8;
    if (MODE == 0) {
        if (!producer) {
#pragma unroll
            for (int dx = 0; dx < 9; dx++) {
                int d = dy*9 + dx;
                float4* outp = (float4*)(g_scores + ((b*ND + d)*NH + gh)*NW + gw);
                outp[0] = make_float4(acc[dx][0], acc[dx][1], acc[dx][2], acc[dx][3]);
                outp[1] = make_float4(acc[dx][4], acc[dx][5], acc[dx][6], acc[dx][7]);
            }
        }
    } else {
        // ---- alpha_den = sum_d sg^2, reduced across the 9 dy-warps --------
        float den[8];
#pragma unroll
        for (int j = 0; j < 8; j++) den[j] = 0.f;
        if (!producer) {
#pragma unroll
            for (int dx = 0; dx < 9; dx++) {
                int d = dy*9 + dx;
                float vp = g_vplus[d], alo = g_alo[d], ahi = g_ahi[d];
                const float4* sp = (const float4*)(g_scores + ((b*ND + d)*NH + gh)*NW + gw);
                float4 sa = sp[0], sb = sp[1];
                float sv[8] = {sa.x,sa.y,sa.z,sa.w, sb.x,sb.y,sb.z,sb.w};
#pragma unroll
                for (int j = 0; j < 8; j++) {
                    float s = sv[j];
                    float sgn = (s > 0.f) ? 1.f : ((s < 0.f) ? -1.f : 0.f);
                    float ga = vp * (alo*sgn + ahi);         // grad_act
                    float sg = ga * acc[dx][j];
                    den[j] = fmaf(sg, sg, den[j]);
                }
            }
        }
        float* denS   = sm;        // reuse staging smem
        float* alphaS = sm + 256;
        __syncthreads();
        if (tid < 256) denS[tid] = 0.f;
        __syncthreads();
        if (!producer) {
#pragma unroll
            for (int j = 0; j < 8; j++)
                atomicAdd(denS + (y*32 + xg*8 + j), den[j]);
        }
        __syncthreads();
        if (tid < 256) {
            int py = tid >> 5, px = tid & 31;
            float num = g_anum[b*NHW + (y0 + py)*NW + x0 + px];
            float dn  = denS[tid];
            alphaS[tid] = g_step * (num / fmaxf(dn + g_reg*num, 1e-8f));
        }
        __syncthreads();
        // ---- fused filter update: fout = fbase - (step*alpha) * f_grad ----
        for (int i = tid; i < 8192; i += 320) {
            int c = i >> 6, rem = i & 63, py = rem >> 3, x4 = rem & 7;
            int gi = ((b*NC + c)*NH + y0 + py)*NW + x0 + x4*4;
            float4 fv4 = *(const float4*)(fbase + gi);
            float4 gv4 = *(const float4*)(fin + gi);     // fin == f_grad here
            float4 sa  = *(const float4*)(alphaS + py*32 + x4*4);
            float4 o;
            o.x = fv4.x - sa.x*gv4.x;
            o.y = fv4.y - sa.y*gv4.y;
            o.z = fv4.z - sa.z*gv4.z;
            o.w = fv4.w - sa.w*gv4.w;
            *(float4*)(fout + gi) = o;
        }
    }
}

// ---------------------------------------------------------------------------
// corr_t_kernel: f_grad(c,p) = reg*f(c,p) + sum_d mapped(d,p)*ref(c,p+d-4)
// R17: 160 threads = 4 compute warps (cg = warp, 4 channels each of a 16-ch
// chunk) + 1 PRODUCER warp doing all cp.async staging. Double-buffered ref
// chunks with two barriers per chunk:
//   syncA: group ci published -> compute; syncB: buffer free -> refill ci+2.
// mapped cache (mS) filled by compute warps during producer's prologue.
// Also writes alpha_num = sum_c f_grad^2 (in-block smem reduction).
// Dynamic smem: (23328 + 2*11264) floats + 160 int2 = 184704 B.
// ---------------------------------------------------------------------------
#define CT_SMEM (45856*4 + 160*8)

__global__ __launch_bounds__(160)
void corr_t_kernel(const float* __restrict__ fin, const float* __restrict__ ref)
{
    extern __shared__ float sm[];
    float* mS = sm;                        // 81*8*36 = 23328 floats
    int2* tbl = (int2*)(sm + 45856);
    const int b  = blockIdx.z;
    const int x0 = blockIdx.x * TX, y0 = blockIdx.y * TY;
    const int tid = threadIdx.x;
    const int cg = tid >> 5;               // 0..3 compute, 4 producer
    const int r  = tid & 31;
    const int y  = r >> 2;
    const int xg = r & 3;
    const bool producer = (cg == 4);
    const float regw = g_reg;

    build_ref_tbl(tbl, tid, 160, x0, y0);
    __syncthreads();                       // table ready

    const float* refb = ref + b*NC*NHW;

    float anum[8];
#pragma unroll
    for (int j = 0; j < 8; j++) anum[j] = 0.f;
    const int gh = y0 + y, gw = x0 + xg*8;

    if (producer) {
        // ---- staging-only warp: 8 groups of 16 channels, double buffer ----
        const int lane = r;
        auto stage = [&](int s, int ch) {
            float* rb_ = sm + 23328 + s*11264;
            const float* rc_ = refb + ch*NHW;
            for (int i = lane; i < 2560; i += 32) {
                int c_ = div160(i);
                int2 t_ = tbl[i - c_*160];
                bool v_ = (t_.x >= 0);
                const float* src_ = v_ ? (rc_ + c_*NHW + t_.x) : rc_;
                cpa16(rb_ + c_*704 + t_.y, src_, v_);
            }
            cp_commit();
        };
        stage(0, 0);
        stage(1, 16);
        for (int ci = 0; ci < 8; ci++) {
            if (ci < 7) cp_wait<1>(); else cp_wait<0>();   // group ci landed
            __syncthreads();   // A: publish buffer ci&1
            __syncthreads();   // B: consumers done with buffer ci&1
            if (ci + 2 < 8) stage(ci & 1, (ci + 2)*16);
        }
    } else {
        // ---- compute warps ----
        // fill mapped = grad_act * (act - v_plus*target), overlapping the
        // producer's prologue staging
        for (int i = tid; i < ND*256; i += 128) {
            int d = i >> 8, p = i & 255, py = p >> 5, px = p & 31;
            float s = g_scores[((b*ND + d)*NH + y0 + py)*NW + x0 + px];
            float vp = g_vplus[d], alo = g_alo[d], ahi = g_ahi[d], tg = g_target[d];
            float sgn = (s > 0.f) ? 1.f : ((s < 0.f) ? -1.f : 0.f);
            float ga  = vp * (alo*sgn + ahi);
            float act = vp * (alo*fabsf(s) + ahi*s);
            mS[d*(TY*FST) + py*FST + px] = ga * (act - vp*tg);
        }

        for (int ci = 0; ci < 8; ci++) {
            __syncthreads();   // A: group ci (and mS on ci=0) ready
            const float* rbuf = sm + 23328 + (ci & 1)*11264;

            float acc[4][8];
#pragma unroll
            for (int a = 0; a < 4; a++)
#pragma unroll
                for (int j = 0; j < 8; j++) acc[a][j] = 0.f;

            for (int dyy = 0; dyy < 9; dyy++) {
                float mv[9][8];
#pragma unroll
                for (int dx = 0; dx < 9; dx++) {
                    const float4* mp = (const float4*)(mS + (dyy*9 + dx)*(TY*FST) + y*FST + xg*8);
                    float4 m0 = mp[0], m1 = mp[1];
                    mv[dx][0]=m0.x; mv[dx][1]=m0.y; mv[dx][2]=m0.z; mv[dx][3]=m0.w;
                    mv[dx][4]=m1.x; mv[dx][5]=m1.y; mv[dx][6]=m1.z; mv[dx][7]=m1.w;
                }
#pragma unroll
                for (int cl = 0; cl < 4; cl++) {
                    const float4* rp = (const float4*)(rbuf + (cg*4 + cl)*704 + (y + dyy)*RST + xg*8);
                    float4 ra = rp[0], rb4 = rp[1], rc4 = rp[2], rd4 = rp[3];
                    float rv[16] = {ra.x,ra.y,ra.z,ra.w, rb4.x,rb4.y,rb4.z,rb4.w,
                                    rc4.x,rc4.y,rc4.z,rc4.w, rd4.x,rd4.y,rd4.z,rd4.w};
#pragma unroll
                    for (int dx = 0; dx < 9; dx++)
#pragma unroll
                        for (int j = 0; j < 8; j++)
                            acc[cl][j] = fmaf(mv[dx][j], rv[dx + j], acc[cl][j]);
                }
            }

            // finalize this chunk's 4 channels: reg*f, write f_grad, alpha_num
#pragma unroll
            for (int cl = 0; cl < 4; cl++) {
                int c = ci*16 + cg*4 + cl;
                int gi = ((b*NC + c)*NH + gh)*NW + gw;
                const float4* fp = (const float4*)(fin + gi);
                float4 fa = fp[0], fb4 = fp[1];
                float fg[8];
                fg[0] = fmaf(regw, fa.x, acc[cl][0]);
                fg[1] = fmaf(regw, fa.y, acc[cl][1]);
                fg[2] = fmaf(regw, fa.z, acc[cl][2]);
                fg[3] = fmaf(regw, fa.w, acc[cl][3]);
                fg[4] = fmaf(regw, fb4.x, acc[cl][4]);
                fg[5] = fmaf(regw, fb4.y, acc[cl][5]);
                fg[6] = fmaf(regw, fb4.z, acc[cl][6]);
                fg[7] = fmaf(regw, fb4.w, acc[cl][7]);
                float4* op = (float4*)(g_fgrad + gi);
                op[0] = make_float4(fg[0], fg[1], fg[2], fg[3]);
                op[1] = make_float4(fg[4], fg[5], fg[6], fg[7]);
#pragma unroll
                for (int j = 0; j < 8; j++) anum[j] = fmaf(fg[j], fg[j], anum[j]);
            }
            __syncthreads();   // B: done with buffer ci&1
        }
    }

    // reduce alpha_num across the 4 compute warps, write to global.
    // (final syncB above guarantees all compute finished; mS reusable)
    float* numS = sm;
    if (tid < 128) { numS[tid] = 0.f; numS[tid + 128] = 0.f; }
    __syncthreads();
    if (!producer) {
#pragma unroll
        for (int j = 0; j < 8; j++)
            atomicAdd(numS + (y*32 + xg*8 + j), anum[j]);
    }
    __syncthreads();
    for (int i = tid; i < 256; i += 160)
        g_anum[b*NHW + (y0 + (i >> 5))*NW + x0 + (i & 31)] = numS[i];
}

// ---------------------------------------------------------------------------
extern "C" void kernel_launch(void* const* d_in, const int* in_sizes, int n_in,
                              void* d_out, int out_size) {
    const float* fmap = (const float*)d_in[0];   // filter_map (b,c,H,W)
    const float* ref  = (const float*)d_in[1];   // reference_feat (b,c,H,W)
    const float* lw   = (const float*)d_in[2];   // label_w (10)
    const float* sw   = (const float*)d_in[3];   // spatial_w (10)
    const float* mw   = (const float*)d_in[4];   // mask_w (10)
    const float* ls   = (const float*)d_in[5];   // log_step_length (1)
    const float* fr   = (const float*)d_in[6];   // filter_reg (1)
    float* out = (float*)d_out;

    cudaFuncSetAttribute(corr_kernel<0>,
                         cudaFuncAttributeMaxDynamicSharedMemorySize, CORR_SMEM);
    cudaFuncSetAttribute(corr_kernel<1>,
                         cudaFuncAttributeMaxDynamicSharedMemorySize, CORR_SMEM);
    cudaFuncSetAttribute(corr_t_kernel,
                         cudaFuncAttributeMaxDynamicSharedMemorySize, CT_SMEM);

    void* p;
    cudaGetSymbolAddress(&p, g_f);     float* gf  = (float*)p;
    cudaGetSymbolAddress(&p, g_fgrad); float* gfg = (float*)p;

    setup_kernel<<<1, 128>>>(lw, sw, mw, ls, fr);

    dim3 grid(NW/TX, NH/TY, NB);   // (4, 16, 4)
    for (int it = 0; it < 3; it++) {
        const float* fin = (it == 0) ? fmap : gf;
        float* fout = (it == 2) ? out : gf;
        corr_kernel<0><<<grid, 320, CORR_SMEM>>>(fin, ref, nullptr, nullptr);  // scores
        corr_t_kernel<<<grid, 160, CT_SMEM>>>(fin, ref);           // f_grad + alpha_num
        corr_kernel<1><<<grid, 320, CORR_SMEM>>>(gfg, ref, fin, fout); // alpha_den + update
    }
}